// round 3
// baseline (speedup 1.0000x reference)
#include <cuda_runtime.h>
#include <cstdint>

// 2-layer LSTM (HID=10), B=2048, T=1024, future=64.
// 10 lanes per element, 3 elements per warp.
// Software-pipelined: iteration i computes layer2(i-1) and layer1(i)
// concurrently (independent given h1(i-1)) to double ILP on the
// latency-bound chain. x-term folded in post-hsum so future-step
// feedback (x = y_prev) only serializes one scalar FMA.

#define HID 10

typedef unsigned long long u64;

__device__ __forceinline__ u64 pk(float a, float b) {
    u64 r; asm("mov.b64 %0, {%1, %2};" : "=l"(r) : "f"(a), "f"(b)); return r;
}
__device__ __forceinline__ float2 upk(u64 v) {
    float2 f; asm("mov.b64 {%0, %1}, %2;" : "=f"(f.x), "=f"(f.y) : "l"(v)); return f;
}
__device__ __forceinline__ u64 ffma2(u64 a, u64 b, u64 c) {
    u64 d; asm("fma.rn.f32x2 %0, %1, %2, %3;" : "=l"(d) : "l"(a), "l"(b), "l"(c)); return d;
}
__device__ __forceinline__ float hsum(u64 v) { float2 f = upk(v); return f.x + f.y; }

__device__ __forceinline__ float fast_ex2(float x) {
    float r; asm("ex2.approx.f32 %0, %1;" : "=f"(r) : "f"(x)); return r;
}
__device__ __forceinline__ float fast_rcp(float x) {
    float r; asm("rcp.approx.f32 %0, %1;" : "=f"(r) : "f"(x)); return r;
}
// A is already -z*log2e : sigmoid(z)
__device__ __forceinline__ float sig_scaled(float A) {
    return fast_rcp(1.0f + fast_ex2(A));
}
// A is already -2z*log2e : tanh(z)
__device__ __forceinline__ float tanh_scaled(float A) {
    return fmaf(fast_rcp(1.0f + fast_ex2(A)), 2.0f, -1.0f);
}
__device__ __forceinline__ float tanh_plain(float c) {
    return tanh_scaled(c * -2.885390081777927f);  // -2*log2(e)
}

__global__ void __launch_bounds__(32, 8)
lstm2_kernel(const float* __restrict__ x,
             const float* __restrict__ Wih1, const float* __restrict__ Whh1,
             const float* __restrict__ bih1, const float* __restrict__ bhh1,
             const float* __restrict__ Wih2, const float* __restrict__ Whh2,
             const float* __restrict__ bih2, const float* __restrict__ bhh2,
             const float* __restrict__ Wlin, const float* __restrict__ blin,
             float* __restrict__ out,
             int B, int T, int TT)
{
    const int lane = threadIdx.x;
    int e = lane / HID;                 // element slot within warp: 0..2 (3 = idle lanes)
    int u = lane - e * HID;             // hidden unit owned by this lane
    const bool lane_ok = (e < 3);
    const int ec = lane_ok ? e : 2;     // idle lanes mirror element slot 2
    const int b = blockIdx.x * 3 + ec;
    const bool b_ok = lane_ok && (b < B);
    const int bc = (b < B) ? b : (B - 1);

    // ---- load + pre-scale weights into registers (one-time) ----
    const float NL  = -1.4426950408889634f;   // -log2(e)   (i, f, o: sigmoid)
    const float N2L = -2.885390081777927f;    // -2*log2(e) (g: tanh)
    const float scl[4] = {NL, NL, N2L, NL};

    u64 Whh1r[4][5], Wih2r[4][5], Whh2r[4][5];
    float bias1[4], bias2[4], wx1[4];
#pragma unroll
    for (int g = 0; g < 4; ++g) {
        const float s = scl[g];
        const int r = g * HID + u;
        bias1[g] = (__ldg(&bih1[r]) + __ldg(&bhh1[r])) * s;
        bias2[g] = (__ldg(&bih2[r]) + __ldg(&bhh2[r])) * s;
        wx1[g]   = __ldg(&Wih1[r]) * s;        // W_ih1 is [40,1]
#pragma unroll
        for (int p = 0; p < 5; ++p) {
            float2 w;
            w = *(const float2*)&Whh1[r * HID + 2 * p]; Whh1r[g][p] = pk(w.x * s, w.y * s);
            w = *(const float2*)&Wih2[r * HID + 2 * p]; Wih2r[g][p] = pk(w.x * s, w.y * s);
            w = *(const float2*)&Whh2[r * HID + 2 * p]; Whh2r[g][p] = pk(w.x * s, w.y * s);
        }
    }
    u64 WL[5];
#pragma unroll
    for (int p = 0; p < 5; ++p) {
        float2 w = *(const float2*)&Wlin[2 * p];
        WL[p] = pk(w.x, w.y);
    }
    const float bl = __ldg(&blin[0]);

    // per-warp exchange buffers (12 floats per element slot, float4-aligned)
    __shared__ float4 s1[3][3];
    __shared__ float4 s2[3][3];

    // state: h1p = h1(i-1) packed, h2p = h2(i-2) packed
    u64 h1p[5], h2p[5];
#pragma unroll
    for (int p = 0; p < 5; ++p) { h1p[p] = 0ull; h2p[p] = 0ull; }
    float c1 = 0.0f, c2 = 0.0f;

    const float* xrow = x + (size_t)bc * T;
    float xcur = __ldg(&xrow[0]);
    float xnext = __ldg(&xrow[1]);

    // ---- prologue: layer1(0) with h1(-1)=0, c1(-1)=0 ----
    {
        float gt1[4];
#pragma unroll
        for (int g = 0; g < 4; ++g) gt1[g] = fmaf(wx1[g], xcur, bias1[g]);
        const float si = sig_scaled(gt1[0]);
        const float sf = sig_scaled(gt1[1]);
        const float tg = tanh_scaled(gt1[2]);
        const float so = sig_scaled(gt1[3]);
        c1 = fmaf(sf, c1, si * tg);
        const float h1u = so * tanh_plain(c1);
        if (lane_ok) ((float*)&s1[ec][0])[u] = h1u;
        __syncwarp();
        float4 A = s1[ec][0], Bv = s1[ec][1], Cv = s1[ec][2];
        h1p[0] = pk(A.x, A.y);  h1p[1] = pk(A.z, A.w);
        h1p[2] = pk(Bv.x, Bv.y); h1p[3] = pk(Bv.z, Bv.w);
        h1p[4] = pk(Cv.x, Cv.y);
    }
    xcur = xnext;

    // ---- pipelined main loop: iteration i computes L2(i-1) and L1(i) ----
    for (int i = 1; i < TT; ++i) {
        float xn = 0.0f;
        if (i + 1 < T) xn = __ldg(&xrow[i + 1]);

        // L2(i-1): Whh2 @ h2(i-2)  [independent chain A]
        u64 a2[4];
#pragma unroll
        for (int g = 0; g < 4; ++g) {
            u64 a = pk(bias2[g], 0.0f);
#pragma unroll
            for (int p = 0; p < 5; ++p) a = ffma2(h2p[p], Whh2r[g][p], a);
            a2[g] = a;
        }
        // L1(i): Whh1 @ h1(i-1)  [independent chain B]
        u64 b1[4];
#pragma unroll
        for (int g = 0; g < 4; ++g) {
            u64 a = pk(bias1[g], 0.0f);
#pragma unroll
            for (int p = 0; p < 5; ++p) a = ffma2(h1p[p], Whh1r[g][p], a);
            b1[g] = a;
        }
        // L2(i-1): Wih2 @ h1(i-1)
#pragma unroll
        for (int g = 0; g < 4; ++g) {
#pragma unroll
            for (int p = 0; p < 5; ++p) a2[g] = ffma2(h1p[p], Wih2r[g][p], a2[g]);
        }

        // L2(i-1) nonlinearities -> h2(i-1)
        {
            const float si = sig_scaled(hsum(a2[0]));
            const float sf = sig_scaled(hsum(a2[1]));
            const float tg = tanh_scaled(hsum(a2[2]));
            const float so = sig_scaled(hsum(a2[3]));
            c2 = fmaf(sf, c2, si * tg);
            const float h2u = so * tanh_plain(c2);
            if (lane_ok) ((float*)&s2[ec][0])[u] = h2u;
        }
        __syncwarp();
        {
            float4 A = s2[ec][0], Bv = s2[ec][1], Cv = s2[ec][2];
            h2p[0] = pk(A.x, A.y);  h2p[1] = pk(A.z, A.w);
            h2p[2] = pk(Bv.x, Bv.y); h2p[3] = pk(Bv.z, Bv.w);
            h2p[4] = pk(Cv.x, Cv.y);       // h2p now = h2(i-1)
        }

        // y(i-1) = h2(i-1) @ W_lin^T + b_lin
        u64 ya = pk(bl, 0.0f);
#pragma unroll
        for (int p = 0; p < 5; ++p) ya = ffma2(h2p[p], WL[p], ya);
        const float y = hsum(ya);
        if (b_ok && u == 0) out[(size_t)bc * TT + (i - 1)] = y;

        // L1(i) finish: fold x-term (only this FMA waits on y in future steps)
        const float xt = (i < T) ? xcur : y;
        {
            const float si = sig_scaled(fmaf(wx1[0], xt, hsum(b1[0])));
            const float sf = sig_scaled(fmaf(wx1[1], xt, hsum(b1[1])));
            const float tg = tanh_scaled(fmaf(wx1[2], xt, hsum(b1[2])));
            const float so = sig_scaled(fmaf(wx1[3], xt, hsum(b1[3])));
            c1 = fmaf(sf, c1, si * tg);
            const float h1u = so * tanh_plain(c1);
            if (lane_ok) ((float*)&s1[ec][0])[u] = h1u;
        }
        __syncwarp();
        {
            float4 A = s1[ec][0], Bv = s1[ec][1], Cv = s1[ec][2];
            h1p[0] = pk(A.x, A.y);  h1p[1] = pk(A.z, A.w);
            h1p[2] = pk(Bv.x, Bv.y); h1p[3] = pk(Bv.z, Bv.w);
            h1p[4] = pk(Cv.x, Cv.y);       // h1p now = h1(i)
        }
        xcur = xn;
    }

    // ---- epilogue: L2(TT-1) and y(TT-1) ----
    {
        u64 a2[4];
#pragma unroll
        for (int g = 0; g < 4; ++g) {
            u64 a = pk(bias2[g], 0.0f);
#pragma unroll
            for (int p = 0; p < 5; ++p) a = ffma2(h2p[p], Whh2r[g][p], a);
#pragma unroll
            for (int p = 0; p < 5; ++p) a = ffma2(h1p[p], Wih2r[g][p], a);
            a2[g] = a;
        }
        const float si = sig_scaled(hsum(a2[0]));
        const float sf = sig_scaled(hsum(a2[1]));
        const float tg = tanh_scaled(hsum(a2[2]));
        const float so = sig_scaled(hsum(a2[3]));
        c2 = fmaf(sf, c2, si * tg);
        const float h2u = so * tanh_plain(c2);
        if (lane_ok) ((float*)&s2[ec][0])[u] = h2u;
        __syncwarp();
        float4 A = s2[ec][0], Bv = s2[ec][1], Cv = s2[ec][2];
        u64 hp0 = pk(A.x, A.y), hp1 = pk(A.z, A.w);
        u64 hp2 = pk(Bv.x, Bv.y), hp3 = pk(Bv.z, Bv.w);
        u64 hp4 = pk(Cv.x, Cv.y);
        u64 ya = pk(bl, 0.0f);
        ya = ffma2(hp0, WL[0], ya); ya = ffma2(hp1, WL[1], ya);
        ya = ffma2(hp2, WL[2], ya); ya = ffma2(hp3, WL[3], ya);
        ya = ffma2(hp4, WL[4], ya);
        const float y = hsum(ya);
        if (b_ok && u == 0) out[(size_t)bc * TT + (TT - 1)] = y;
    }
}

extern "C" void kernel_launch(void* const* d_in, const int* in_sizes, int n_in,
                              void* d_out, int out_size)
{
    const int B  = 2048;
    const int T  = in_sizes[0] / B;     // 1024
    const int TT = out_size / B;        // T + future = 1088

    const float* x    = (const float*)d_in[0];
    const float* Wih1 = (const float*)d_in[1];
    const float* Whh1 = (const float*)d_in[2];
    const float* bih1 = (const float*)d_in[3];
    const float* bhh1 = (const float*)d_in[4];
    const float* Wih2 = (const float*)d_in[5];
    const float* Whh2 = (const float*)d_in[6];
    const float* bih2 = (const float*)d_in[7];
    const float* bhh2 = (const float*)d_in[8];
    const float* Wlin = (const float*)d_in[9];
    const float* blin = (const float*)d_in[10];
    float* out = (float*)d_out;

    const int grid = (B + 2) / 3;       // 683 warps, 3 elements each
    lstm2_kernel<<<grid, 32>>>(x, Wih1, Whh1, bih1, bhh1,
                               Wih2, Whh2, bih2, bhh2,
                               Wlin, blin, out, B, T, TT);
}

// round 5
// speedup vs baseline: 1.4856x; 1.4856x over previous
#include <cuda_runtime.h>
#include <cstdint>

// 2-layer LSTM (HID=10), B=2048, T=1024, future=64.
// 10 lanes per element, 3 elements per warp.
// R3: tanh.approx.f32 for all nonlinearities (sigmoid via 0.5*tanh(z/2)+0.5,
// the 0.5 pre-folded into i/f/o weight rows), shfl-based h broadcast
// (no smem, no WARPSYNC on the chain), and float4 x prefetch 4 steps ahead
// with the T-loop and future-loop split.

#define HID 10

typedef unsigned long long u64;

__device__ __forceinline__ u64 pk(float a, float b) {
    u64 r; asm("mov.b64 %0, {%1, %2};" : "=l"(r) : "f"(a), "f"(b)); return r;
}
__device__ __forceinline__ float2 upk(u64 v) {
    float2 f; asm("mov.b64 {%0, %1}, %2;" : "=f"(f.x), "=f"(f.y) : "l"(v)); return f;
}
__device__ __forceinline__ u64 ffma2(u64 a, u64 b, u64 c) {
    u64 d; asm("fma.rn.f32x2 %0, %1, %2, %3;" : "=l"(d) : "l"(a), "l"(b), "l"(c)); return d;
}
__device__ __forceinline__ float hsum(u64 v) { float2 f = upk(v); return f.x + f.y; }

__device__ __forceinline__ float tanh_fast(float z) {
    float r; asm("tanh.approx.f32 %0, %1;" : "=f"(r) : "f"(z)); return r;
}
// A is already z/2 : sigmoid(z) = 0.5*tanh(z/2) + 0.5
__device__ __forceinline__ float sig_half(float A) {
    return fmaf(tanh_fast(A), 0.5f, 0.5f);
}

__global__ void __launch_bounds__(32, 8)
lstm2_kernel(const float* __restrict__ x,
             const float* __restrict__ Wih1, const float* __restrict__ Whh1,
             const float* __restrict__ bih1, const float* __restrict__ bhh1,
             const float* __restrict__ Wih2, const float* __restrict__ Whh2,
             const float* __restrict__ bih2, const float* __restrict__ bhh2,
             const float* __restrict__ Wlin, const float* __restrict__ blin,
             float* __restrict__ out,
             int B, int T, int TT)
{
    const int lane = threadIdx.x;
    int e = lane / HID;                 // element slot within warp: 0..2 (3 = idle lanes)
    int u = lane - e * HID;             // hidden unit owned by this lane
    const bool lane_ok = (e < 3);
    const int ec = lane_ok ? e : 2;     // idle lanes mirror element slot 2
    const int g0 = ec * HID;            // first lane of this element's group
    const int b = blockIdx.x * 3 + ec;
    const bool wr = lane_ok && (b < B) && (u == 0);
    const int bc = (b < B) ? b : (B - 1);

    // ---- load + pre-scale weights into registers (one-time) ----
    // i, f, o rows scaled by 0.5 (sigmoid-via-tanh); g row unscaled (plain tanh)
    const float scl[4] = {0.5f, 0.5f, 1.0f, 0.5f};

    u64 Whh1r[4][5], Wih2r[4][5], Whh2r[4][5];
    float bias1[4], bias2[4], wx1[4];
#pragma unroll
    for (int g = 0; g < 4; ++g) {
        const float s = scl[g];
        const int r = g * HID + u;
        bias1[g] = (__ldg(&bih1[r]) + __ldg(&bhh1[r])) * s;
        bias2[g] = (__ldg(&bih2[r]) + __ldg(&bhh2[r])) * s;
        wx1[g]   = __ldg(&Wih1[r]) * s;        // W_ih1 is [40,1]
#pragma unroll
        for (int p = 0; p < 5; ++p) {
            float2 w;
            w = *(const float2*)&Whh1[r * HID + 2 * p]; Whh1r[g][p] = pk(w.x * s, w.y * s);
            w = *(const float2*)&Wih2[r * HID + 2 * p]; Wih2r[g][p] = pk(w.x * s, w.y * s);
            w = *(const float2*)&Whh2[r * HID + 2 * p]; Whh2r[g][p] = pk(w.x * s, w.y * s);
        }
    }
    u64 WL[5];
#pragma unroll
    for (int p = 0; p < 5; ++p) {
        float2 w = *(const float2*)&Wlin[2 * p];
        WL[p] = pk(w.x, w.y);
    }
    const float bl = __ldg(&blin[0]);

    // state
    u64 h1p[5], h2p[5];
#pragma unroll
    for (int p = 0; p < 5; ++p) { h1p[p] = 0ull; h2p[p] = 0ull; }
    float c1 = 0.0f, c2 = 0.0f;

    // all-gather 10 h values of this element's group into packed pairs
    auto bcast = [&](float v, u64* hp) {
        const unsigned m = 0xffffffffu;
        float v0 = __shfl_sync(m, v, g0 + 0);
        float v1 = __shfl_sync(m, v, g0 + 1);
        float v2 = __shfl_sync(m, v, g0 + 2);
        float v3 = __shfl_sync(m, v, g0 + 3);
        float v4 = __shfl_sync(m, v, g0 + 4);
        float v5 = __shfl_sync(m, v, g0 + 5);
        float v6 = __shfl_sync(m, v, g0 + 6);
        float v7 = __shfl_sync(m, v, g0 + 7);
        float v8 = __shfl_sync(m, v, g0 + 8);
        float v9 = __shfl_sync(m, v, g0 + 9);
        hp[0] = pk(v0, v1); hp[1] = pk(v2, v3); hp[2] = pk(v4, v5);
        hp[3] = pk(v6, v7); hp[4] = pk(v8, v9);
    };

    // one full LSTM step; returns y(t)
    auto step = [&](float xt) -> float {
        // L2, h2-dependent half (independent of layer-1 chain)
        u64 a2[4];
#pragma unroll
        for (int g = 0; g < 4; ++g) {
            u64 a = pk(bias2[g], 0.0f);
#pragma unroll
            for (int p = 0; p < 5; ++p) a = ffma2(h2p[p], Whh2r[g][p], a);
            a2[g] = a;
        }
        // layer 1
        float gt1[4];
#pragma unroll
        for (int g = 0; g < 4; ++g) {
            u64 a = pk(fmaf(wx1[g], xt, bias1[g]), 0.0f);
#pragma unroll
            for (int p = 0; p < 5; ++p) a = ffma2(h1p[p], Whh1r[g][p], a);
            gt1[g] = hsum(a);
        }
        {
            const float si = sig_half(gt1[0]);
            const float sf = sig_half(gt1[1]);
            const float tg = tanh_fast(gt1[2]);
            const float so = sig_half(gt1[3]);
            c1 = fmaf(sf, c1, si * tg);
            const float h1u = so * tanh_fast(c1);
            bcast(h1u, h1p);
        }
        // L2, h1-dependent half
        float gt2[4];
#pragma unroll
        for (int g = 0; g < 4; ++g) {
            u64 a = a2[g];
#pragma unroll
            for (int p = 0; p < 5; ++p) a = ffma2(h1p[p], Wih2r[g][p], a);
            gt2[g] = hsum(a);
        }
        {
            const float si = sig_half(gt2[0]);
            const float sf = sig_half(gt2[1]);
            const float tg = tanh_fast(gt2[2]);
            const float so = sig_half(gt2[3]);
            c2 = fmaf(sf, c2, si * tg);
            const float h2u = so * tanh_fast(c2);
            bcast(h2u, h2p);
        }
        // y = h2 @ W_lin^T + b_lin (every lane computes it; needed for future loop)
        u64 ya = pk(bl, 0.0f);
#pragma unroll
        for (int p = 0; p < 5; ++p) ya = ffma2(h2p[p], WL[p], ya);
        return hsum(ya);
    };

    const float* xrow = x + (size_t)bc * T;
    float* orow = out + (size_t)bc * TT;

    float y = 0.0f;
    int t = 0;

    // ---- main T loop: float4 x stream, prefetched one chunk (4 steps) ahead ----
    const int T4 = T & ~3;
    if ((((uintptr_t)xrow) & 15u) == 0 && T4 > 0) {
        const float4* xq = (const float4*)xrow;
        const int nc = T4 >> 2;
        float4 xv = __ldg(&xq[0]);
        for (int ci = 0; ci < nc; ++ci) {
            float4 xn = make_float4(0.f, 0.f, 0.f, 0.f);
            if (ci + 1 < nc) xn = __ldg(&xq[ci + 1]);
            y = step(xv.x); if (wr) orow[t + 0] = y;
            y = step(xv.y); if (wr) orow[t + 1] = y;
            y = step(xv.z); if (wr) orow[t + 2] = y;
            y = step(xv.w); if (wr) orow[t + 3] = y;
            xv = xn; t += 4;
        }
    }
    // scalar tail (handles misaligned or T%4 != 0; no-op for T=1024)
    for (; t < T; ++t) {
        y = step(__ldg(&xrow[t]));
        if (wr) orow[t] = y;
    }
    // ---- future loop: x(t) = y(t-1), known to every lane ----
    for (; t < TT; ++t) {
        y = step(y);
        if (wr) orow[t] = y;
    }
}

extern "C" void kernel_launch(void* const* d_in, const int* in_sizes, int n_in,
                              void* d_out, int out_size)
{
    const int B  = 2048;
    const int T  = in_sizes[0] / B;     // 1024
    const int TT = out_size / B;        // T + future = 1088

    const float* x    = (const float*)d_in[0];
    const float* Wih1 = (const float*)d_in[1];
    const float* Whh1 = (const float*)d_in[2];
    const float* bih1 = (const float*)d_in[3];
    const float* bhh1 = (const float*)d_in[4];
    const float* Wih2 = (const float*)d_in[5];
    const float* Whh2 = (const float*)d_in[6];
    const float* bih2 = (const float*)d_in[7];
    const float* bhh2 = (const float*)d_in[8];
    const float* Wlin = (const float*)d_in[9];
    const float* blin = (const float*)d_in[10];
    float* out = (float*)d_out;

    const int grid = (B + 2) / 3;       // 683 warps, 3 elements each
    lstm2_kernel<<<grid, 32>>>(x, Wih1, Whh1, bih1, bhh1,
                               Wih2, Whh2, bih2, bhh2,
                               Wlin, blin, out, B, T, TT);
}